// round 13
// baseline (speedup 1.0000x reference)
#include <cuda_runtime.h>
#include <cuda_bf16.h>
#include <math.h>
#include <stdint.h>

// Problem constants
#define BB 32
#define TT 1024
#define HH 512
#define VV 1024
#define SS 128
#define LL 257          // 2*S + 1
#define PST 132         // compact row stride (floats): 128 odd entries + blank + pad

// GEMM tile config: 256x128 CTA tile, warp tile 64x64, BK=64
#define BM 256
#define BN 128
#define BK 64
#define ASTR 72                          // halves per padded tile row (144 B)
#define A_TILE_B (BM * ASTR * 2)         // 36864 bytes
#define B_TILE_B (BN * ASTR * 2)         // 18432 bytes
#define STG_B (A_TILE_B + B_TILE_B)      // 55296 bytes per stage
#define NSTG 3
#define GSM (NSTG * STG_B)               // 165888 bytes dynamic smem

#define SLSTR 129                        // floats per staged-logits row
#define SL_BYTES (BM * SLSTR * 4)        // 132096
#define LIST_OFF SL_BYTES

// Scratch (device globals: allocation-free per harness rules)
__device__ __nv_bfloat16 g_Xb[(size_t)BB * TT * HH];   // 32 MB : X bf16 (K-major)
__device__ __nv_bfloat16 g_W1t[(size_t)HH * HH];       // W1^T bf16 [N][K]
__device__ __nv_bfloat16 g_W2t[(size_t)VV * HH];       // W2^T bf16 [N][K]
__device__ __nv_bfloat16 g_hb[(size_t)BB * TT * HH];   // 32 MB : tanh(X@W1+b1) bf16
__device__ float2 g_part[(size_t)BB * TT][16];         // 4 MB  : per-row (max, sumexp)
__device__ float g_gath[(size_t)BB * TT * PST + 64];   // 17 MB : gathered logits
__device__ float g_p2[(size_t)BB * TT * PST + 64];     // 17 MB : compact probs

// ---------------------------------------------------------------------------
// PTX helpers
// ---------------------------------------------------------------------------
__device__ __forceinline__ unsigned su32(const void* p) {
    unsigned a;
    asm("{ .reg .u64 t; cvta.to.shared.u64 t, %1; cvt.u32.u64 %0, t; }" : "=r"(a) : "l"(p));
    return a;
}
__device__ __forceinline__ void cp16(unsigned dst, const void* src) {
    asm volatile("cp.async.cg.shared.global [%0], [%1], 16;" :: "r"(dst), "l"(src));
}
__device__ __forceinline__ void cp_commit() { asm volatile("cp.async.commit_group;" ::: "memory"); }
__device__ __forceinline__ void cp_wait1()  { asm volatile("cp.async.wait_group 1;" ::: "memory"); }
__device__ __forceinline__ void cp_wait0()  { asm volatile("cp.async.wait_group 0;" ::: "memory"); }

__device__ __forceinline__ void ldm_x4(unsigned* r, unsigned addr) {
    asm volatile("ldmatrix.sync.aligned.m8n8.x4.shared.b16 {%0,%1,%2,%3}, [%4];"
        : "=r"(r[0]), "=r"(r[1]), "=r"(r[2]), "=r"(r[3]) : "r"(addr));
}
__device__ __forceinline__ void mma16816(float* c, const unsigned* a, const unsigned* b) {
    asm volatile(
        "mma.sync.aligned.m16n8k16.row.col.f32.bf16.bf16.f32 "
        "{%0,%1,%2,%3}, {%4,%5,%6,%7}, {%8,%9}, {%0,%1,%2,%3};"
        : "+f"(c[0]), "+f"(c[1]), "+f"(c[2]), "+f"(c[3])
        : "r"(a[0]), "r"(a[1]), "r"(a[2]), "r"(a[3]), "r"(b[0]), "r"(b[1]));
}
__device__ __forceinline__ float tanh_fast(float x) {
    float y;
    asm("tanh.approx.f32 %0, %1;" : "=f"(y) : "f"(x));
    return y;
}

// ---------------------------------------------------------------------------
// Conversion kernels
// ---------------------------------------------------------------------------
__global__ void __launch_bounds__(256)
f2bf_kernel(const float* __restrict__ in, __nv_bfloat16* __restrict__ out, int n) {
    int i = (blockIdx.x * 256 + threadIdx.x) * 4;
    if (i < n) {
        float4 v = *reinterpret_cast<const float4*>(in + i);
        *reinterpret_cast<__nv_bfloat162*>(out + i)     = __floats2bfloat162_rn(v.x, v.y);
        *reinterpret_cast<__nv_bfloat162*>(out + i + 2) = __floats2bfloat162_rn(v.z, v.w);
    }
}

// transpose + convert: in [K][N] fp32 row-major -> out [N][K] bf16 row-major
__global__ void __launch_bounds__(256)
f2bfT_kernel(const float* __restrict__ in, __nv_bfloat16* __restrict__ out, int K, int N) {
    __shared__ float tile[32][33];
    const int n0 = blockIdx.x * 32, k0 = blockIdx.y * 32;
    const int tx = threadIdx.x & 31, ty = threadIdx.x >> 5;
#pragma unroll
    for (int i = 0; i < 32; i += 8)
        tile[ty + i][tx] = in[(size_t)(k0 + ty + i) * N + n0 + tx];
    __syncthreads();
#pragma unroll
    for (int i = 0; i < 32; i += 8)
        out[(size_t)(n0 + ty + i) * K + k0 + tx] = __float2bfloat16(tile[tx][ty + i]);
}

// ---------------------------------------------------------------------------
// Shared GEMM mainloop: 256x128 tile, BK=64, 3-stage cp.async, single barrier
// per chunk. Leaves logits+bias in acc[4][8][4].
// ---------------------------------------------------------------------------
struct GemmCtx {
    unsigned sbase;
    int lane, warp, wm, wn, gid, tig, row0, col0;
    unsigned aoff[4], boff[4];
    const __nv_bfloat16 *Ap, *Bp;
    int brow_g0;

    __device__ __forceinline__ void init(const __nv_bfloat16* A, const __nv_bfloat16* BT,
                                         unsigned sb) {
        sbase = sb;
        const int tid = threadIdx.x;
        lane = tid & 31; warp = tid >> 5;
        wm = warp & 3;   wn = warp >> 2;
        gid = lane >> 2; tig = lane & 3;
        row0 = blockIdx.y * BM; col0 = blockIdx.x * BN;
        const int l8 = lane & 7, j = lane >> 3;
#pragma unroll
        for (int mt = 0; mt < 4; mt++) {
            const int r = wm * 64 + mt * 16 + (j & 1) * 8 + l8;
            aoff[mt] = (unsigned)((r * ASTR + (j >> 1) * 8) * 2);
        }
#pragma unroll
        for (int np = 0; np < 4; np++) {
            const int r = wn * 64 + np * 16 + (j >> 1) * 8 + l8;
            boff[np] = (unsigned)((r * ASTR + (j & 1) * 8) * 2);
        }
        Ap = A  + (size_t)(row0 + tid) * HH;             // A: one row per thread
        Bp = BT + (size_t)(col0 + (tid >> 1)) * HH;      // B: two threads per row
        brow_g0 = (tid & 1) * 4;
    }

    __device__ __forceinline__ void issue(int c) {
        const unsigned abase = sbase + (unsigned)(c % NSTG) * STG_B;
        const unsigned bbase = abase + A_TILE_B;
        const int k0 = c * BK;
        const unsigned arow = (unsigned)(threadIdx.x * ASTR * 2);
#pragma unroll
        for (int g = 0; g < 8; g++)
            cp16(abase + arow + (unsigned)g * 16u, Ap + k0 + g * 8);
        const unsigned browo = (unsigned)((threadIdx.x >> 1) * ASTR * 2);
#pragma unroll
        for (int g = 0; g < 4; g++) {
            const int kk = (brow_g0 + g) * 8;
            cp16(bbase + browo + (unsigned)(brow_g0 + g) * 16u, Bp + k0 + kk);
        }
        cp_commit();
    }

    __device__ __forceinline__ void run(float (&acc)[4][8][4], const float* bias) {
#pragma unroll
        for (int mt = 0; mt < 4; mt++)
#pragma unroll
            for (int nt = 0; nt < 8; nt++)
#pragma unroll
                for (int e = 0; e < 4; e++) acc[mt][nt][e] = 0.f;

        issue(0); issue(1);
        const int NC = HH / BK;   // 8
#pragma unroll 1
        for (int c = 0; c < NC; ++c) {
            if (c < NC - 1) cp_wait1(); else cp_wait0();
            __syncthreads();
            if (c + 2 < NC) issue(c + 2);

            const unsigned Au = sbase + (unsigned)(c % NSTG) * STG_B;
            const unsigned Bu = Au + A_TILE_B;
#pragma unroll
            for (int kk = 0; kk < BK / 16; kk++) {
                const unsigned kbb = (unsigned)(kk * 32);
                unsigned af[4][4];
#pragma unroll
                for (int mt = 0; mt < 4; mt++)
                    ldm_x4(af[mt], Au + aoff[mt] + kbb);
                unsigned bf[4][4];
#pragma unroll
                for (int np = 0; np < 4; np++)
                    ldm_x4(bf[np], Bu + boff[np] + kbb);
#pragma unroll
                for (int mt = 0; mt < 4; mt++)
#pragma unroll
                    for (int nt = 0; nt < 8; nt++)
                        mma16816(acc[mt][nt], af[mt], &bf[nt >> 1][(nt & 1) * 2]);
            }
        }
        // add bias
#pragma unroll
        for (int mt = 0; mt < 4; mt++)
#pragma unroll
            for (int nt = 0; nt < 8; nt++) {
                const int col = col0 + wn * 64 + nt * 8 + tig * 2;
                const float bx = bias[col], by = bias[col + 1];
                acc[mt][nt][0] += bx; acc[mt][nt][1] += by;
                acc[mt][nt][2] += bx; acc[mt][nt][3] += by;
            }
    }
};

// ---------------------------------------------------------------------------
// GEMM1: h = tanh(X@W1+b1), bf16 output
// ---------------------------------------------------------------------------
__global__ void __launch_bounds__(256, 1)
gemm1_kernel(const __nv_bfloat16* __restrict__ A, const __nv_bfloat16* __restrict__ BT,
             const float* __restrict__ bias, __nv_bfloat16* __restrict__ Cb) {
    extern __shared__ __align__(16) char smraw[];
    GemmCtx cx;
    cx.init(A, BT, su32(smraw));
    float acc[4][8][4];
    cx.run(acc, bias);

#pragma unroll
    for (int mt = 0; mt < 4; mt++)
#pragma unroll
        for (int nt = 0; nt < 8; nt++) {
            const int col = cx.col0 + cx.wn * 64 + nt * 8 + cx.tig * 2;
            const int r0 = cx.row0 + cx.wm * 64 + mt * 16 + cx.gid;
            const int r1 = r0 + 8;
            __nv_bfloat162 p01 = __floats2bfloat162_rn(tanh_fast(acc[mt][nt][0]),
                                                       tanh_fast(acc[mt][nt][1]));
            __nv_bfloat162 p23 = __floats2bfloat162_rn(tanh_fast(acc[mt][nt][2]),
                                                       tanh_fast(acc[mt][nt][3]));
            *reinterpret_cast<__nv_bfloat162*>(Cb + (size_t)r0 * HH + col) = p01;
            *reinterpret_cast<__nv_bfloat162*>(Cb + (size_t)r1 * HH + col) = p23;
        }
}

// ---------------------------------------------------------------------------
// GEMM2 fused: logits stay on-chip. Emits (max,sumexp) partials + gathered
// logit values at this CTA's target labels. NO global logits array.
// ---------------------------------------------------------------------------
__global__ void __launch_bounds__(256, 1)
gemm2_fused(const __nv_bfloat16* __restrict__ A, const __nv_bfloat16* __restrict__ BT,
            const float* __restrict__ bias, const int* __restrict__ targets) {
    extern __shared__ __align__(16) char smraw[];
    GemmCtx cx;
    cx.init(A, BT, su32(smraw));
    float acc[4][8][4];
    cx.run(acc, bias);

    const int lane = cx.lane, warp = cx.warp, wm = cx.wm, wn = cx.wn;
    const int gid = cx.gid, tig = cx.tig, row0 = cx.row0, col0 = cx.col0;

    // ---- per-row (max, sumexp) partials over this warp's 64-col span
#pragma unroll
    for (int mt = 0; mt < 4; mt++) {
#pragma unroll
        for (int half = 0; half < 2; half++) {
            float m = -INFINITY;
#pragma unroll
            for (int nt = 0; nt < 8; nt++)
                m = fmaxf(m, fmaxf(acc[mt][nt][half * 2], acc[mt][nt][half * 2 + 1]));
            float s = 0.f;
#pragma unroll
            for (int nt = 0; nt < 8; nt++)
                s += __expf(acc[mt][nt][half * 2] - m) + __expf(acc[mt][nt][half * 2 + 1] - m);
#pragma unroll
            for (int o = 1; o <= 2; o <<= 1) {
                const float mo = __shfl_xor_sync(0xffffffffu, m, o);
                const float so = __shfl_xor_sync(0xffffffffu, s, o);
                const float mn = fmaxf(m, mo);
                s = s * __expf(m - mn) + so * __expf(mo - mn);
                m = mn;
            }
            if (tig == 0) {
                const int row = row0 + wm * 64 + mt * 16 + half * 8 + gid;
                g_part[row][blockIdx.x * 2 + wn] = make_float2(m, s);
            }
        }
    }

    // ---- stage logits block to smem (pipeline stages are dead after a barrier)
    __syncthreads();
    float* sl = reinterpret_cast<float*>(smraw);
#pragma unroll
    for (int mt = 0; mt < 4; mt++)
#pragma unroll
        for (int nt = 0; nt < 8; nt++) {
            const int c = wn * 64 + nt * 8 + tig * 2;
            const int r0 = wm * 64 + mt * 16 + gid;
            const int r1 = r0 + 8;
            sl[r0 * SLSTR + c]     = acc[mt][nt][0];
            sl[r0 * SLSTR + c + 1] = acc[mt][nt][1];
            sl[r1 * SLSTR + c]     = acc[mt][nt][2];
            sl[r1 * SLSTR + c + 1] = acc[mt][nt][3];
        }

    // ---- warp 0: compact list of label indices landing in [col0, col0+BN)
    const int b = row0 >> 10;                 // T = 1024
    const int* tg = targets + (b << 7);
    int* s_cnt  = reinterpret_cast<int*>(smraw + LIST_OFF);
    int* s_list = s_cnt + 4;
    if (warp == 0) {
        int cnt = 0;
        const unsigned lt = (1u << lane) - 1u;
#pragma unroll
        for (int it = 0; it < 4; it++) {
            const int i = it * 32 + lane;
            const int lab = tg[i];
            const bool in = (lab >= col0) && (lab < col0 + BN);
            const unsigned mask = __ballot_sync(0xffffffffu, in);
            if (in) s_list[cnt + __popc(mask & lt)] = (i << 16) | (lab - col0);
            cnt += __popc(mask);
        }
        if (lane == 0) *s_cnt = cnt;
    }
    __syncthreads();
    const int cnt = *s_cnt;

    // ---- scatter gathered logits: 8 warps x 32 rows
#pragma unroll 1
    for (int rr = 0; rr < 32; rr++) {
        const int r = warp * 32 + rr;
        float* grow = g_gath + (size_t)(row0 + r) * PST;
        for (int e = lane; e < cnt; e += 32) {
            const int packed = s_list[e];
            grow[packed >> 16] = sl[r * SLSTR + (packed & 0xffff)];
        }
        if (col0 == 0 && lane == 0) grow[128] = sl[r * SLSTR];   // blank = col 0
    }
}

// ---------------------------------------------------------------------------
// lse from partials + p = exp(gath - lse). Warp per row; fully coalesced.
// ---------------------------------------------------------------------------
__global__ void __launch_bounds__(256)
lse_finish_kernel() {
    const int warp = threadIdx.x >> 5;
    const int lane = threadIdx.x & 31;
    const int row  = (blockIdx.x << 3) + warp;

    float m = -INFINITY, s = 0.f;
    if (lane < 16) {
        const float2 p = g_part[row][lane];
        m = p.x; s = p.y;
    }
#pragma unroll
    for (int o = 16; o > 0; o >>= 1) {
        const float mo = __shfl_xor_sync(0xffffffffu, m, o);
        const float so = __shfl_xor_sync(0xffffffffu, s, o);
        const float mn = fmaxf(m, mo);
        s = s * __expf(m - mn) + so * __expf(mo - mn);
        m = mn;
    }
    const float lse = m + logf(s);

    const float* gr = g_gath + (size_t)row * PST;
    float* pr = g_p2 + (size_t)row * PST;
    const float4 v = reinterpret_cast<const float4*>(gr)[lane];
    float4 p;
    p.x = expf(v.x - lse); p.y = expf(v.y - lse);
    p.z = expf(v.z - lse); p.w = expf(v.w - lse);
    reinterpret_cast<float4*>(pr)[lane] = p;
    if (lane == 0) pr[128] = expf(gr[128] - lse);
}

// ---------------------------------------------------------------------------
// Linear-domain CTC forward scan: one WARP per batch element.
// ---------------------------------------------------------------------------
__global__ void __launch_bounds__(32)
ctc_lin_kernel(const int* __restrict__ targets, const int* __restrict__ input_lengths,
               float* __restrict__ out) {
    const int b    = blockIdx.x;
    const int lane = threadIdx.x;
    const int* tg  = targets + b * SS;
    const float* base = g_p2 + (size_t)b * TT * PST;
    const int Tlen = input_lengths[b];

    float c1 = 0.f, c3 = 0.f, c5 = 0.f, c7 = 0.f;
    {
        const int s1 = lane * 8 + 1;
        if (s1 >= 3)            c1 = (tg[s1 >> 1] != tg[(s1 >> 1) - 1]) ? 1.f : 0.f;
        const int s3 = lane * 8 + 3;
        c3 = (tg[s3 >> 1] != tg[(s3 >> 1) - 1]) ? 1.f : 0.f;
        const int s5 = lane * 8 + 5;
        c5 = (tg[s5 >> 1] != tg[(s5 >> 1) - 1]) ? 1.f : 0.f;
        const int s7 = lane * 8 + 7;
        c7 = (tg[s7 >> 1] != tg[(s7 >> 1) - 1]) ? 1.f : 0.f;
    }

    const float init_sc = __int_as_float((100 + 127) << 23);
    float r[9];
#pragma unroll
    for (int j = 0; j < 9; j++) r[j] = 0.f;
    if (lane == 0) {
        r[0] = base[128] * init_sc;   // s=0 blank
        r[1] = base[0]   * init_sc;   // s=1 first label
    }
    int Esum = 100;

    float4 F0, F1, F2, F3;
    float  P0, P1, P2, P3;

#define LOADSLOT(Ff, Pf, tp_) do {                                            \
        int tp = (tp_); if (tp > Tlen - 1) tp = Tlen - 1;                     \
        const float* rp = base + (size_t)tp * PST;                            \
        Ff = *reinterpret_cast<const float4*>(rp + lane * 4);                 \
        Pf = rp[128];                                                         \
    } while (0)

#define STEP(Ff, Pf) do {                                                     \
        float u1 = __shfl_up_sync(0xffffffffu, r[7], 1);                      \
        if (lane == 0) u1 = 0.f;                                              \
        float n0 = (r[0] + u1) * Pf;                                          \
        float n1 = fmaf(c1, u1,   r[1] + r[0]) * Ff.x;                        \
        float n2 = (r[2] + r[1]) * Pf;                                        \
        float n3 = fmaf(c3, r[1], r[3] + r[2]) * Ff.y;                        \
        float n4 = (r[4] + r[3]) * Pf;                                        \
        float n5 = fmaf(c5, r[3], r[5] + r[4]) * Ff.z;                        \
        float n6 = (r[6] + r[5]) * Pf;                                        \
        float n7 = fmaf(c7, r[5], r[7] + r[6]) * Ff.w;                        \
        float n8 = (r[8] + r[7]) * Pf;                                        \
        r[0]=n0; r[1]=n1; r[2]=n2; r[3]=n3; r[4]=n4;                          \
        r[5]=n5; r[6]=n6; r[7]=n7;                                            \
        r[8] = (lane == 31) ? n8 : 0.f;                                       \
    } while (0)

#define RENORM() do {                                                         \
        float m = r[0];                                                       \
        m = fmaxf(m, r[1]); m = fmaxf(m, r[2]); m = fmaxf(m, r[3]);           \
        m = fmaxf(m, r[4]); m = fmaxf(m, r[5]); m = fmaxf(m, r[6]);           \
        m = fmaxf(m, r[7]); m = fmaxf(m, r[8]);                               \
        m = fmaxf(m, __shfl_xor_sync(0xffffffffu, m, 16));                    \
        m = fmaxf(m, __shfl_xor_sync(0xffffffffu, m, 8));                     \
        m = fmaxf(m, __shfl_xor_sync(0xffffffffu, m, 4));                     \
        m = fmaxf(m, __shfl_xor_sync(0xffffffffu, m, 2));                    \
        m = fmaxf(m, __shfl_xor_sync(0xffffffffu, m, 1));                    \
        int ex = (__float_as_int(m) >> 23) & 255;                             \
        int se = 60 - (ex - 127);                                             \
        se = (se > 127) ? 127 : ((se < -126) ? -126 : se);                    \
        const float sc = __int_as_float((se + 127) << 23);                    \
        r[0]*=sc; r[1]*=sc; r[2]*=sc; r[3]*=sc; r[4]*=sc;                     \
        r[5]*=sc; r[6]*=sc; r[7]*=sc; r[8]*=sc;                               \
        Esum += se;                                                           \
    } while (0)

    int t = 1;
    LOADSLOT(F0, P0, 1);
    LOADSLOT(F1, P1, 2);
    LOADSLOT(F2, P2, 3);
    LOADSLOT(F3, P3, 4);

    if (Tlen > 1) {
        for (;;) {
            STEP(F0, P0); LOADSLOT(F0, P0, t + 4);
            if (++t >= Tlen) break;
            if ((t & 7) == 0) RENORM();
            STEP(F1, P1); LOADSLOT(F1, P1, t + 4);
            if (++t >= Tlen) break;
            if ((t & 7) == 0) RENORM();
            STEP(F2, P2); LOADSLOT(F2, P2, t + 4);
            if (++t >= Tlen) break;
            if ((t & 7) == 0) RENORM();
            STEP(F3, P3); LOADSLOT(F3, P3, t + 4);
            if (++t >= Tlen) break;
            if ((t & 7) == 0) RENORM();
        }
    }

    __shared__ float fin[260];
#pragma unroll
    for (int j = 0; j < 8; j++) fin[lane * 8 + j] = r[j];
    if (lane == 31) fin[256] = r[8];
    __syncwarp();

    int cnt = 0;
#pragma unroll
    for (int i = 0; i < 4; i++) cnt += (tg[lane + i * 32] != 0);
#pragma unroll
    for (int o = 16; o > 0; o >>= 1) cnt += __shfl_xor_sync(0xffffffffu, cnt, o);
    const int sb = cnt;

    if (lane == 0) {
        const float e = fin[2 * sb - 1] + fin[2 * sb];
        out[b] = ((float)Esum * 0.6931471805599453f - logf(e)) / (float)sb;
    }
}

// ---------------------------------------------------------------------------
extern "C" void kernel_launch(void* const* d_in, const int* in_sizes, int n_in,
                              void* d_out, int out_size) {
    const int*   targets = (const int*)  d_in[0];
    const float* X       = (const float*)d_in[1];
    const int*   ilen    = (const int*)  d_in[2];
    const float* W1      = (const float*)d_in[3];
    const float* b1      = (const float*)d_in[4];
    const float* W2      = (const float*)d_in[5];
    const float* b2      = (const float*)d_in[6];
    float*       out     = (float*)d_out;

    const int M = BB * TT;  // 32768

    __nv_bfloat16 *xb, *w1t, *w2t, *hb;
    cudaGetSymbolAddress((void**)&xb,  g_Xb);
    cudaGetSymbolAddress((void**)&w1t, g_W1t);
    cudaGetSymbolAddress((void**)&w2t, g_W2t);
    cudaGetSymbolAddress((void**)&hb,  g_hb);

    f2bf_kernel<<<(M * HH) / (256 * 4), 256>>>(X, xb, M * HH);
    f2bfT_kernel<<<dim3(HH / 32, HH / 32), 256>>>(W1, w1t, HH, HH);
    f2bfT_kernel<<<dim3(VV / 32, HH / 32), 256>>>(W2, w2t, HH, VV);

    cudaFuncSetAttribute(gemm1_kernel, cudaFuncAttributeMaxDynamicSharedMemorySize, GSM);
    cudaFuncSetAttribute(gemm2_fused,  cudaFuncAttributeMaxDynamicSharedMemorySize, GSM);

    gemm1_kernel<<<dim3(HH / BN, M / BM), 256, GSM>>>(xb, w1t, b1, hb);
    gemm2_fused<<<dim3(VV / BN, M / BM), 256, GSM>>>(hb, w2t, b2, targets);

    lse_finish_kernel<<<M / 8, 256>>>();

    ctc_lin_kernel<<<BB, 32>>>(targets, ilen, out);
}

// round 14
// speedup vs baseline: 1.2429x; 1.2429x over previous
#include <cuda_runtime.h>
#include <cuda_bf16.h>
#include <math.h>
#include <stdint.h>

// Problem constants
#define BB 32
#define TT 1024
#define HH 512
#define VV 1024
#define SS 128
#define LL 257          // 2*S + 1
#define PST 132         // compact row stride (floats): 128 odd entries + blank + pad

// GEMM tile config (R11 proven config: 128x128, 2 CTAs/SM)
#define BK 64
#define ASTR 72                      // halves per padded tile row (144 B)
#define TILE_H (128 * ASTR)          // halves per tile
#define NSTG 3
#define STG_B (2 * TILE_H * 2)       // bytes per stage (A+B) = 36864
#define GSM (NSTG * STG_B)           // 110592 bytes dynamic smem

#define SLSTR 129                    // floats per staged-logits row
#define SL_BYTES (128 * SLSTR * 4)   // 66048
#define LIST_OFF SL_BYTES

// Scratch (device globals: allocation-free per harness rules)
__device__ __nv_bfloat16 g_Xb[(size_t)BB * TT * HH];   // 32 MB : X bf16 (K-major)
__device__ __nv_bfloat16 g_W1t[(size_t)HH * HH];       // W1^T bf16 [N][K]
__device__ __nv_bfloat16 g_W2t[(size_t)VV * HH];       // W2^T bf16 [N][K]
__device__ __nv_bfloat16 g_hb[(size_t)BB * TT * HH];   // 32 MB : tanh(X@W1+b1) bf16
__device__ float2 g_part[(size_t)BB * TT][16];         // 4 MB  : per-row (max, sumexp)
__device__ float g_gath[(size_t)BB * TT * PST + 64];   // 17 MB : gathered logits
__device__ float g_p2[(size_t)BB * TT * PST + 64];     // 17 MB : compact probs

// ---------------------------------------------------------------------------
// PTX helpers
// ---------------------------------------------------------------------------
__device__ __forceinline__ unsigned su32(const void* p) {
    unsigned a;
    asm("{ .reg .u64 t; cvta.to.shared.u64 t, %1; cvt.u32.u64 %0, t; }" : "=r"(a) : "l"(p));
    return a;
}
__device__ __forceinline__ void cp16(unsigned dst, const void* src) {
    asm volatile("cp.async.cg.shared.global [%0], [%1], 16;" :: "r"(dst), "l"(src));
}
__device__ __forceinline__ void cp_commit() { asm volatile("cp.async.commit_group;" ::: "memory"); }
__device__ __forceinline__ void cp_wait1()  { asm volatile("cp.async.wait_group 1;" ::: "memory"); }
__device__ __forceinline__ void cp_wait0()  { asm volatile("cp.async.wait_group 0;" ::: "memory"); }

__device__ __forceinline__ void ldm_x4(unsigned* r, unsigned addr) {
    asm volatile("ldmatrix.sync.aligned.m8n8.x4.shared.b16 {%0,%1,%2,%3}, [%4];"
        : "=r"(r[0]), "=r"(r[1]), "=r"(r[2]), "=r"(r[3]) : "r"(addr));
}
__device__ __forceinline__ void mma16816(float* c, const unsigned* a, const unsigned* b) {
    asm volatile(
        "mma.sync.aligned.m16n8k16.row.col.f32.bf16.bf16.f32 "
        "{%0,%1,%2,%3}, {%4,%5,%6,%7}, {%8,%9}, {%0,%1,%2,%3};"
        : "+f"(c[0]), "+f"(c[1]), "+f"(c[2]), "+f"(c[3])
        : "r"(a[0]), "r"(a[1]), "r"(a[2]), "r"(a[3]), "r"(b[0]), "r"(b[1]));
}
__device__ __forceinline__ float tanh_fast(float x) {
    float y;
    asm("tanh.approx.f32 %0, %1;" : "=f"(y) : "f"(x));
    return y;
}

// ---------------------------------------------------------------------------
// Conversion kernels
// ---------------------------------------------------------------------------
__global__ void __launch_bounds__(256)
f2bf_kernel(const float* __restrict__ in, __nv_bfloat16* __restrict__ out, int n) {
    int i = (blockIdx.x * 256 + threadIdx.x) * 4;
    if (i < n) {
        float4 v = *reinterpret_cast<const float4*>(in + i);
        *reinterpret_cast<__nv_bfloat162*>(out + i)     = __floats2bfloat162_rn(v.x, v.y);
        *reinterpret_cast<__nv_bfloat162*>(out + i + 2) = __floats2bfloat162_rn(v.z, v.w);
    }
}

// transpose + convert: in [K][N] fp32 row-major -> out [N][K] bf16 row-major
__global__ void __launch_bounds__(256)
f2bfT_kernel(const float* __restrict__ in, __nv_bfloat16* __restrict__ out, int K, int N) {
    __shared__ float tile[32][33];
    const int n0 = blockIdx.x * 32, k0 = blockIdx.y * 32;
    const int tx = threadIdx.x & 31, ty = threadIdx.x >> 5;
#pragma unroll
    for (int i = 0; i < 32; i += 8)
        tile[ty + i][tx] = in[(size_t)(k0 + ty + i) * N + n0 + tx];
    __syncthreads();
#pragma unroll
    for (int i = 0; i < 32; i += 8)
        out[(size_t)(n0 + ty + i) * K + k0 + tx] = __float2bfloat16(tile[tx][ty + i]);
}

// ---------------------------------------------------------------------------
// Shared GEMM mainloop: 128x128 tile, BK=64, 3-stage cp.async, single barrier
// per chunk. Leaves logits+bias in acc[2][8][4].
// ---------------------------------------------------------------------------
template <int KDIM>
struct GemmCtx {
    unsigned sbase;
    int lane, warp, wm, wn, gid, tig, row0, col0;
    unsigned aoff[2], boff[4];
    const __nv_bfloat16 *Ap, *Bp;
    int frow, fg0;

    __device__ __forceinline__ void init(const __nv_bfloat16* A, const __nv_bfloat16* BT,
                                         unsigned sb) {
        sbase = sb;
        const int tid = threadIdx.x;
        lane = tid & 31; warp = tid >> 5;
        wm = warp & 3;   wn = warp >> 2;
        gid = lane >> 2; tig = lane & 3;
        row0 = blockIdx.y * 128; col0 = blockIdx.x * 128;
        const int l8 = lane & 7, j = lane >> 3;
#pragma unroll
        for (int mt = 0; mt < 2; mt++) {
            const int r = wm * 32 + mt * 16 + (j & 1) * 8 + l8;
            aoff[mt] = (unsigned)((r * ASTR + (j >> 1) * 8) * 2);
        }
#pragma unroll
        for (int np = 0; np < 4; np++) {
            const int r = wn * 64 + np * 16 + (j >> 1) * 8 + l8;
            boff[np] = (unsigned)((r * ASTR + (j & 1) * 8) * 2);
        }
        frow = tid >> 1; fg0 = (tid & 1) * 4;
        Ap = A  + (size_t)(row0 + frow) * KDIM;
        Bp = BT + (size_t)(col0 + frow) * KDIM;
    }

    __device__ __forceinline__ void issue(int c) {
        const unsigned abase = sbase + (unsigned)(c % NSTG) * STG_B;
        const unsigned bbase = abase + TILE_H * 2u;
        const unsigned rowoff = (unsigned)(frow * ASTR * 2);
        const int k0 = c * BK;
#pragma unroll
        for (int g = 0; g < 4; g++) {
            const int kk = (fg0 + g) * 8;
            cp16(abase + rowoff + (unsigned)(fg0 + g) * 16u, Ap + k0 + kk);
            cp16(bbase + rowoff + (unsigned)(fg0 + g) * 16u, Bp + k0 + kk);
        }
        cp_commit();
    }

    __device__ __forceinline__ void run(float (&acc)[2][8][4], const float* bias) {
#pragma unroll
        for (int mt = 0; mt < 2; mt++)
#pragma unroll
            for (int nt = 0; nt < 8; nt++)
#pragma unroll
                for (int e = 0; e < 4; e++) acc[mt][nt][e] = 0.f;

        issue(0); issue(1);
        const int NC = KDIM / BK;
#pragma unroll 1
        for (int c = 0; c < NC; ++c) {
            if (c < NC - 1) cp_wait1(); else cp_wait0();
            __syncthreads();
            if (c + 2 < NC) issue(c + 2);

            const unsigned Au = sbase + (unsigned)(c % NSTG) * STG_B;
            const unsigned Bu = Au + TILE_H * 2u;
#pragma unroll
            for (int kk = 0; kk < BK / 16; kk++) {
                const unsigned kbb = (unsigned)(kk * 32);
                unsigned af[2][4];
                ldm_x4(af[0], Au + aoff[0] + kbb);
                ldm_x4(af[1], Au + aoff[1] + kbb);
                unsigned bf[4][4];
#pragma unroll
                for (int np = 0; np < 4; np++)
                    ldm_x4(bf[np], Bu + boff[np] + kbb);
#pragma unroll
                for (int mt = 0; mt < 2; mt++)
#pragma unroll
                    for (int nt = 0; nt < 8; nt++)
                        mma16816(acc[mt][nt], af[mt], &bf[nt >> 1][(nt & 1) * 2]);
            }
        }
        // add bias
#pragma unroll
        for (int mt = 0; mt < 2; mt++)
#pragma unroll
            for (int nt = 0; nt < 8; nt++) {
                const int col = col0 + wn * 64 + nt * 8 + tig * 2;
                const float bx = bias[col], by = bias[col + 1];
                acc[mt][nt][0] += bx; acc[mt][nt][1] += by;
                acc[mt][nt][2] += bx; acc[mt][nt][3] += by;
            }
    }
};

// ---------------------------------------------------------------------------
// GEMM1: h = tanh(X@W1+b1), bf16 output
// ---------------------------------------------------------------------------
__global__ void __launch_bounds__(256)
gemm1_kernel(const __nv_bfloat16* __restrict__ A, const __nv_bfloat16* __restrict__ BT,
             const float* __restrict__ bias, __nv_bfloat16* __restrict__ Cb) {
    extern __shared__ __align__(16) char smraw[];
    GemmCtx<HH> cx;
    cx.init(A, BT, su32(smraw));
    float acc[2][8][4];
    cx.run(acc, bias);

#pragma unroll
    for (int mt = 0; mt < 2; mt++)
#pragma unroll
        for (int nt = 0; nt < 8; nt++) {
            const int col = cx.col0 + cx.wn * 64 + nt * 8 + cx.tig * 2;
            const int r0 = cx.row0 + cx.wm * 32 + mt * 16 + cx.gid;
            const int r1 = r0 + 8;
            __nv_bfloat162 p01 = __floats2bfloat162_rn(tanh_fast(acc[mt][nt][0]),
                                                       tanh_fast(acc[mt][nt][1]));
            __nv_bfloat162 p23 = __floats2bfloat162_rn(tanh_fast(acc[mt][nt][2]),
                                                       tanh_fast(acc[mt][nt][3]));
            *reinterpret_cast<__nv_bfloat162*>(Cb + (size_t)r0 * HH + col) = p01;
            *reinterpret_cast<__nv_bfloat162*>(Cb + (size_t)r1 * HH + col) = p23;
        }
}

// ---------------------------------------------------------------------------
// GEMM2 fused: logits stay on-chip. Emits (max,sumexp) partials + gathered
// logit values at this CTA's target labels. NO global logits array.
// ---------------------------------------------------------------------------
__global__ void __launch_bounds__(256)
gemm2_fused(const __nv_bfloat16* __restrict__ A, const __nv_bfloat16* __restrict__ BT,
            const float* __restrict__ bias, const int* __restrict__ targets) {
    extern __shared__ __align__(16) char smraw[];
    GemmCtx<HH> cx;
    cx.init(A, BT, su32(smraw));
    float acc[2][8][4];
    cx.run(acc, bias);

    const int lane = cx.lane, warp = cx.warp, wm = cx.wm, wn = cx.wn;
    const int gid = cx.gid, tig = cx.tig, row0 = cx.row0, col0 = cx.col0;

    // ---- per-row (max, sumexp) partials over this warp's 64-col span
#pragma unroll
    for (int mt = 0; mt < 2; mt++) {
#pragma unroll
        for (int half = 0; half < 2; half++) {
            float m = -INFINITY;
#pragma unroll
            for (int nt = 0; nt < 8; nt++)
                m = fmaxf(m, fmaxf(acc[mt][nt][half * 2], acc[mt][nt][half * 2 + 1]));
            float s = 0.f;
#pragma unroll
            for (int nt = 0; nt < 8; nt++)
                s += __expf(acc[mt][nt][half * 2] - m) + __expf(acc[mt][nt][half * 2 + 1] - m);
#pragma unroll
            for (int o = 1; o <= 2; o <<= 1) {
                const float mo = __shfl_xor_sync(0xffffffffu, m, o);
                const float so = __shfl_xor_sync(0xffffffffu, s, o);
                const float mn = fmaxf(m, mo);
                s = s * __expf(m - mn) + so * __expf(mo - mn);
                m = mn;
            }
            if (tig == 0) {
                const int row = row0 + wm * 32 + mt * 16 + gid + half * 8;
                g_part[row][blockIdx.x * 2 + wn] = make_float2(m, s);
            }
        }
    }

    // ---- stage logits block to smem (pipeline stages are dead after a barrier)
    __syncthreads();
    float* sl = reinterpret_cast<float*>(smraw);
#pragma unroll
    for (int mt = 0; mt < 2; mt++)
#pragma unroll
        for (int nt = 0; nt < 8; nt++) {
            const int c = wn * 64 + nt * 8 + tig * 2;
            const int r0 = wm * 32 + mt * 16 + gid;
            const int r1 = r0 + 8;
            sl[r0 * SLSTR + c]     = acc[mt][nt][0];
            sl[r0 * SLSTR + c + 1] = acc[mt][nt][1];
            sl[r1 * SLSTR + c]     = acc[mt][nt][2];
            sl[r1 * SLSTR + c + 1] = acc[mt][nt][3];
        }

    // ---- warp 0: compact list of label indices landing in [col0, col0+128)
    const int b = row0 >> 10;                 // T = 1024
    const int* tg = targets + (b << 7);
    int* s_cnt  = reinterpret_cast<int*>(smraw + LIST_OFF);
    int* s_list = s_cnt + 4;
    if (warp == 0) {
        int cnt = 0;
        const unsigned lt = (1u << lane) - 1u;
#pragma unroll
        for (int it = 0; it < 4; it++) {
            const int i = it * 32 + lane;
            const int lab = tg[i];
            const bool in = (lab >= col0) && (lab < col0 + 128);
            const unsigned mask = __ballot_sync(0xffffffffu, in);
            if (in) s_list[cnt + __popc(mask & lt)] = (i << 16) | (lab - col0);
            cnt += __popc(mask);
        }
        if (lane == 0) *s_cnt = cnt;
    }
    __syncthreads();
    const int cnt = *s_cnt;

    // ---- scatter gathered logits: 8 warps x 16 rows
#pragma unroll 1
    for (int rr = 0; rr < 16; rr++) {
        const int r = warp * 16 + rr;
        float* grow = g_gath + (size_t)(row0 + r) * PST;
        for (int e = lane; e < cnt; e += 32) {
            const int packed = s_list[e];
            grow[packed >> 16] = sl[r * SLSTR + (packed & 0xffff)];
        }
        if (col0 == 0 && lane == 0) grow[128] = sl[r * SLSTR];   // blank = col 0
    }
}

// ---------------------------------------------------------------------------
// lse from partials + p = exp(gath - lse). Warp per row; fully coalesced.
// ---------------------------------------------------------------------------
__global__ void __launch_bounds__(256)
lse_finish_kernel() {
    const int warp = threadIdx.x >> 5;
    const int lane = threadIdx.x & 31;
    const int row  = (blockIdx.x << 3) + warp;

    float m = -INFINITY, s = 0.f;
    if (lane < 16) {
        const float2 p = g_part[row][lane];
        m = p.x; s = p.y;
    }
#pragma unroll
    for (int o = 16; o > 0; o >>= 1) {
        const float mo = __shfl_xor_sync(0xffffffffu, m, o);
        const float so = __shfl_xor_sync(0xffffffffu, s, o);
        const float mn = fmaxf(m, mo);
        s = s * __expf(m - mn) + so * __expf(mo - mn);
        m = mn;
    }
    const float lse = m + logf(s);

    const float* gr = g_gath + (size_t)row * PST;
    float* pr = g_p2 + (size_t)row * PST;
    const float4 v = reinterpret_cast<const float4*>(gr)[lane];
    float4 p;
    p.x = expf(v.x - lse); p.y = expf(v.y - lse);
    p.z = expf(v.z - lse); p.w = expf(v.w - lse);
    reinterpret_cast<float4*>(pr)[lane] = p;
    if (lane == 0) pr[128] = expf(gr[128] - lse);
}

// ---------------------------------------------------------------------------
// Linear-domain CTC forward scan: one WARP per batch element.
// 8-slot register prefetch ring (~480 cyc cover vs ~250-580 cyc L2/DRAM lat).
// ---------------------------------------------------------------------------
__global__ void __launch_bounds__(32)
ctc_lin_kernel(const int* __restrict__ targets, const int* __restrict__ input_lengths,
               float* __restrict__ out) {
    const int b    = blockIdx.x;
    const int lane = threadIdx.x;
    const int* tg  = targets + b * SS;
    const float* base = g_p2 + (size_t)b * TT * PST;
    const int Tlen = input_lengths[b];

    float c1 = 0.f, c3 = 0.f, c5 = 0.f, c7 = 0.f;
    {
        const int s1 = lane * 8 + 1;
        if (s1 >= 3)            c1 = (tg[s1 >> 1] != tg[(s1 >> 1) - 1]) ? 1.f : 0.f;
        const int s3 = lane * 8 + 3;
        c3 = (tg[s3 >> 1] != tg[(s3 >> 1) - 1]) ? 1.f : 0.f;
        const int s5 = lane * 8 + 5;
        c5 = (tg[s5 >> 1] != tg[(s5 >> 1) - 1]) ? 1.f : 0.f;
        const int s7 = lane * 8 + 7;
        c7 = (tg[s7 >> 1] != tg[(s7 >> 1) - 1]) ? 1.f : 0.f;
    }

    const float init_sc = __int_as_float((100 + 127) << 23);
    float r[9];
#pragma unroll
    for (int j = 0; j < 9; j++) r[j] = 0.f;
    if (lane == 0) {
        r[0] = base[128] * init_sc;   // s=0 blank
        r[1] = base[0]   * init_sc;   // s=1 first label
    }
    int Esum = 100;

    float4 F[8];
    float  P[8];

#define LOADSLOT(i, tp_) do {                                                 \
        int tp = (tp_); if (tp > Tlen - 1) tp = Tlen - 1;                     \
        const float* rp = base + (size_t)tp * PST;                            \
        F[i] = *reinterpret_cast<const float4*>(rp + lane * 4);               \
        P[i] = rp[128];                                                       \
    } while (0)

// s-1 for j=0 AND s-2 for j=1 are BOTH the previous lane's r[7] (= u1).
#define STEP(i) do {                                                          \
        const float4 Ff = F[i]; const float Pf = P[i];                        \
        float u1 = __shfl_up_sync(0xffffffffu, r[7], 1);                      \
        if (lane == 0) u1 = 0.f;                                              \
        float n0 = (r[0] + u1) * Pf;                                          \
        float n1 = fmaf(c1, u1,   r[1] + r[0]) * Ff.x;                        \
        float n2 = (r[2] + r[1]) * Pf;                                        \
        float n3 = fmaf(c3, r[1], r[3] + r[2]) * Ff.y;                        \
        float n4 = (r[4] + r[3]) * Pf;                                        \
        float n5 = fmaf(c5, r[3], r[5] + r[4]) * Ff.z;                        \
        float n6 = (r[6] + r[5]) * Pf;                                        \
        float n7 = fmaf(c7, r[5], r[7] + r[6]) * Ff.w;                        \
        float n8 = (r[8] + r[7]) * Pf;                                        \
        r[0]=n0; r[1]=n1; r[2]=n2; r[3]=n3; r[4]=n4;                          \
        r[5]=n5; r[6]=n6; r[7]=n7;                                            \
        r[8] = (lane == 31) ? n8 : 0.f;                                       \
    } while (0)

#define RENORM() do {                                                         \
        float m = r[0];                                                       \
        m = fmaxf(m, r[1]); m = fmaxf(m, r[2]); m = fmaxf(m, r[3]);           \
        m = fmaxf(m, r[4]); m = fmaxf(m, r[5]); m = fmaxf(m, r[6]);           \
        m = fmaxf(m, r[7]); m = fmaxf(m, r[8]);                               \
        m = fmaxf(m, __shfl_xor_sync(0xffffffffu, m, 16));                    \
        m = fmaxf(m, __shfl_xor_sync(0xffffffffu, m, 8));                     \
        m = fmaxf(m, __shfl_xor_sync(0xffffffffu, m, 4));                     \
        m = fmaxf(m, __shfl_xor_sync(0xffffffffu, m, 2));                    \
        m = fmaxf(m, __shfl_xor_sync(0xffffffffu, m, 1));                    \
        int ex = (__float_as_int(m) >> 23) & 255;                             \
        int se = 60 - (ex - 127);                                             \
        se = (se > 127) ? 127 : ((se < -126) ? -126 : se);                    \
        const float sc = __int_as_float((se + 127) << 23);                    \
        r[0]*=sc; r[1]*=sc; r[2]*=sc; r[3]*=sc; r[4]*=sc;                     \
        r[5]*=sc; r[6]*=sc; r[7]*=sc; r[8]*=sc;                               \
        Esum += se;                                                           \
    } while (0)

    int t = 1;
#pragma unroll
    for (int i = 0; i < 8; i++) LOADSLOT(i, 1 + i);

    if (Tlen > 1) {
        bool run = true;
        while (run) {
#pragma unroll
            for (int i = 0; i < 8; i++) {
                STEP(i);
                LOADSLOT(i, t + 8);
                if (++t >= Tlen) { run = false; break; }
                if ((t & 7) == 0) RENORM();
            }
        }
    }

    __shared__ float fin[260];
#pragma unroll
    for (int j = 0; j < 8; j++) fin[lane * 8 + j] = r[j];
    if (lane == 31) fin[256] = r[8];
    __syncwarp();

    int cnt = 0;
#pragma unroll
    for (int i = 0; i < 4; i++) cnt += (tg[lane + i * 32] != 0);
#pragma unroll
    for (int o = 16; o > 0; o >>= 1) cnt += __shfl_xor_sync(0xffffffffu, cnt, o);
    const int sb = cnt;

    if (lane == 0) {
        const float e = fin[2 * sb - 1] + fin[2 * sb];
        out[b] = ((float)Esum * 0.6931471805599453f - logf(e)) / (float)sb;
    }
}

// ---------------------------------------------------------------------------
extern "C" void kernel_launch(void* const* d_in, const int* in_sizes, int n_in,
                              void* d_out, int out_size) {
    const int*   targets = (const int*)  d_in[0];
    const float* X       = (const float*)d_in[1];
    const int*   ilen    = (const int*)  d_in[2];
    const float* W1      = (const float*)d_in[3];
    const float* b1      = (const float*)d_in[4];
    const float* W2      = (const float*)d_in[5];
    const float* b2      = (const float*)d_in[6];
    float*       out     = (float*)d_out;

    const int M = BB * TT;  // 32768

    __nv_bfloat16 *xb, *w1t, *w2t, *hb;
    cudaGetSymbolAddress((void**)&xb,  g_Xb);
    cudaGetSymbolAddress((void**)&w1t, g_W1t);
    cudaGetSymbolAddress((void**)&w2t, g_W2t);
    cudaGetSymbolAddress((void**)&hb,  g_hb);

    f2bf_kernel<<<(M * HH) / (256 * 4), 256>>>(X, xb, M * HH);
    f2bfT_kernel<<<dim3(HH / 32, HH / 32), 256>>>(W1, w1t, HH, HH);
    f2bfT_kernel<<<dim3(VV / 32, HH / 32), 256>>>(W2, w2t, HH, VV);

    cudaFuncSetAttribute(gemm1_kernel, cudaFuncAttributeMaxDynamicSharedMemorySize, GSM);
    cudaFuncSetAttribute(gemm2_fused,  cudaFuncAttributeMaxDynamicSharedMemorySize, GSM);

    gemm1_kernel<<<dim3(HH / 128, M / 128), 256, GSM>>>(xb, w1t, b1, hb);
    gemm2_fused<<<dim3(VV / 128, M / 128), 256, GSM>>>(hb, w2t, b2, targets);

    lse_finish_kernel<<<M / 8, 256>>>();

    ctc_lin_kernel<<<BB, 32>>>(targets, ilen, out);
}

// round 15
// speedup vs baseline: 1.3560x; 1.0910x over previous
#include <cuda_runtime.h>
#include <cuda_bf16.h>
#include <math.h>
#include <stdint.h>

// Problem constants
#define BB 32
#define TT 1024
#define HH 512
#define VV 1024
#define SS 128
#define LL 257          // 2*S + 1
#define PST 132         // compact row stride (floats): 128 odd entries + blank + pad

// GEMM tile config (proven config: 128x128, 2 CTAs/SM)
#define BK 64
#define ASTR 72                      // halves per padded tile row (144 B)
#define TILE_H (128 * ASTR)          // halves per tile
#define NSTG 3
#define STG_B (2 * TILE_H * 2)       // bytes per stage (A+B) = 36864
#define GSM (NSTG * STG_B)           // 110592 bytes dynamic smem

#define SLSTR 129                    // floats per staged-logits row
#define SL_BYTES (128 * SLSTR * 4)   // 66048
#define LIST_OFF SL_BYTES

// Scratch (device globals: allocation-free per harness rules)
__device__ __nv_bfloat16 g_Xb[(size_t)BB * TT * HH];   // 32 MB : X bf16 (K-major)
__device__ __nv_bfloat16 g_W1t[(size_t)HH * HH];       // W1^T bf16 [N][K]
__device__ __nv_bfloat16 g_W2t[(size_t)VV * HH];       // W2^T bf16 [N][K]
__device__ __nv_bfloat16 g_hb[(size_t)BB * TT * HH];   // 32 MB : tanh(X@W1+b1) bf16
__device__ float2 g_part[(size_t)BB * TT][16];         // 4 MB  : per-row (max, sumexp)
__device__ float g_gath[(size_t)BB * TT * PST + 64];   // 17 MB : gathered logits
__device__ float g_p2[(size_t)BB * TT * PST + 64];     // 17 MB : compact probs

// ---------------------------------------------------------------------------
// PTX helpers
// ---------------------------------------------------------------------------
__device__ __forceinline__ unsigned su32(const void* p) {
    unsigned a;
    asm("{ .reg .u64 t; cvta.to.shared.u64 t, %1; cvt.u32.u64 %0, t; }" : "=r"(a) : "l"(p));
    return a;
}
__device__ __forceinline__ void cp16(unsigned dst, const void* src) {
    asm volatile("cp.async.cg.shared.global [%0], [%1], 16;" :: "r"(dst), "l"(src));
}
__device__ __forceinline__ void cp_commit() { asm volatile("cp.async.commit_group;" ::: "memory"); }
__device__ __forceinline__ void cp_wait1()  { asm volatile("cp.async.wait_group 1;" ::: "memory"); }
__device__ __forceinline__ void cp_wait0()  { asm volatile("cp.async.wait_group 0;" ::: "memory"); }

__device__ __forceinline__ void ldm_x4(unsigned* r, unsigned addr) {
    asm volatile("ldmatrix.sync.aligned.m8n8.x4.shared.b16 {%0,%1,%2,%3}, [%4];"
        : "=r"(r[0]), "=r"(r[1]), "=r"(r[2]), "=r"(r[3]) : "r"(addr));
}
__device__ __forceinline__ void mma16816(float* c, const unsigned* a, const unsigned* b) {
    asm volatile(
        "mma.sync.aligned.m16n8k16.row.col.f32.bf16.bf16.f32 "
        "{%0,%1,%2,%3}, {%4,%5,%6,%7}, {%8,%9}, {%0,%1,%2,%3};"
        : "+f"(c[0]), "+f"(c[1]), "+f"(c[2]), "+f"(c[3])
        : "r"(a[0]), "r"(a[1]), "r"(a[2]), "r"(a[3]), "r"(b[0]), "r"(b[1]));
}
__device__ __forceinline__ float tanh_fast(float x) {
    float y;
    asm("tanh.approx.f32 %0, %1;" : "=f"(y) : "f"(x));
    return y;
}

// ---------------------------------------------------------------------------
// Conversion kernels
// ---------------------------------------------------------------------------
__global__ void __launch_bounds__(256)
f2bf_kernel(const float* __restrict__ in, __nv_bfloat16* __restrict__ out, int n) {
    int i = (blockIdx.x * 256 + threadIdx.x) * 4;
    if (i < n) {
        float4 v = *reinterpret_cast<const float4*>(in + i);
        *reinterpret_cast<__nv_bfloat162*>(out + i)     = __floats2bfloat162_rn(v.x, v.y);
        *reinterpret_cast<__nv_bfloat162*>(out + i + 2) = __floats2bfloat162_rn(v.z, v.w);
    }
}

// transpose + convert: in [K][N] fp32 row-major -> out [N][K] bf16 row-major
__global__ void __launch_bounds__(256)
f2bfT_kernel(const float* __restrict__ in, __nv_bfloat16* __restrict__ out, int K, int N) {
    __shared__ float tile[32][33];
    const int n0 = blockIdx.x * 32, k0 = blockIdx.y * 32;
    const int tx = threadIdx.x & 31, ty = threadIdx.x >> 5;
#pragma unroll
    for (int i = 0; i < 32; i += 8)
        tile[ty + i][tx] = in[(size_t)(k0 + ty + i) * N + n0 + tx];
    __syncthreads();
#pragma unroll
    for (int i = 0; i < 32; i += 8)
        out[(size_t)(n0 + ty + i) * K + k0 + tx] = __float2bfloat16(tile[tx][ty + i]);
}

// ---------------------------------------------------------------------------
// Shared GEMM mainloop: 128x128 tile, BK=64, 3-stage cp.async, single barrier
// per chunk. Leaves logits+bias in acc[2][8][4].
// ---------------------------------------------------------------------------
template <int KDIM>
struct GemmCtx {
    unsigned sbase;
    int lane, warp, wm, wn, gid, tig, row0, col0;
    unsigned aoff[2], boff[4];
    const __nv_bfloat16 *Ap, *Bp;
    int frow, fg0;

    __device__ __forceinline__ void init(const __nv_bfloat16* A, const __nv_bfloat16* BT,
                                         unsigned sb) {
        sbase = sb;
        const int tid = threadIdx.x;
        lane = tid & 31; warp = tid >> 5;
        wm = warp & 3;   wn = warp >> 2;
        gid = lane >> 2; tig = lane & 3;
        row0 = blockIdx.y * 128; col0 = blockIdx.x * 128;
        const int l8 = lane & 7, j = lane >> 3;
#pragma unroll
        for (int mt = 0; mt < 2; mt++) {
            const int r = wm * 32 + mt * 16 + (j & 1) * 8 + l8;
            aoff[mt] = (unsigned)((r * ASTR + (j >> 1) * 8) * 2);
        }
#pragma unroll
        for (int np = 0; np < 4; np++) {
            const int r = wn * 64 + np * 16 + (j >> 1) * 8 + l8;
            boff[np] = (unsigned)((r * ASTR + (j & 1) * 8) * 2);
        }
        frow = tid >> 1; fg0 = (tid & 1) * 4;
        Ap = A  + (size_t)(row0 + frow) * KDIM;
        Bp = BT + (size_t)(col0 + frow) * KDIM;
    }

    __device__ __forceinline__ void issue(int c) {
        const unsigned abase = sbase + (unsigned)(c % NSTG) * STG_B;
        const unsigned bbase = abase + TILE_H * 2u;
        const unsigned rowoff = (unsigned)(frow * ASTR * 2);
        const int k0 = c * BK;
#pragma unroll
        for (int g = 0; g < 4; g++) {
            const int kk = (fg0 + g) * 8;
            cp16(abase + rowoff + (unsigned)(fg0 + g) * 16u, Ap + k0 + kk);
            cp16(bbase + rowoff + (unsigned)(fg0 + g) * 16u, Bp + k0 + kk);
        }
        cp_commit();
    }

    __device__ __forceinline__ void run(float (&acc)[2][8][4], const float* bias) {
#pragma unroll
        for (int mt = 0; mt < 2; mt++)
#pragma unroll
            for (int nt = 0; nt < 8; nt++)
#pragma unroll
                for (int e = 0; e < 4; e++) acc[mt][nt][e] = 0.f;

        issue(0); issue(1);
        const int NC = KDIM / BK;
#pragma unroll 1
        for (int c = 0; c < NC; ++c) {
            if (c < NC - 1) cp_wait1(); else cp_wait0();
            __syncthreads();
            if (c + 2 < NC) issue(c + 2);

            const unsigned Au = sbase + (unsigned)(c % NSTG) * STG_B;
            const unsigned Bu = Au + TILE_H * 2u;
#pragma unroll
            for (int kk = 0; kk < BK / 16; kk++) {
                const unsigned kbb = (unsigned)(kk * 32);
                unsigned af[2][4];
                ldm_x4(af[0], Au + aoff[0] + kbb);
                ldm_x4(af[1], Au + aoff[1] + kbb);
                unsigned bf[4][4];
#pragma unroll
                for (int np = 0; np < 4; np++)
                    ldm_x4(bf[np], Bu + boff[np] + kbb);
#pragma unroll
                for (int mt = 0; mt < 2; mt++)
#pragma unroll
                    for (int nt = 0; nt < 8; nt++)
                        mma16816(acc[mt][nt], af[mt], &bf[nt >> 1][(nt & 1) * 2]);
            }
        }
        // add bias
#pragma unroll
        for (int mt = 0; mt < 2; mt++)
#pragma unroll
            for (int nt = 0; nt < 8; nt++) {
                const int col = col0 + wn * 64 + nt * 8 + tig * 2;
                const float bx = bias[col], by = bias[col + 1];
                acc[mt][nt][0] += bx; acc[mt][nt][1] += by;
                acc[mt][nt][2] += bx; acc[mt][nt][3] += by;
            }
    }
};

// ---------------------------------------------------------------------------
// GEMM1: h = tanh(X@W1+b1), bf16 output
// ---------------------------------------------------------------------------
__global__ void __launch_bounds__(256)
gemm1_kernel(const __nv_bfloat16* __restrict__ A, const __nv_bfloat16* __restrict__ BT,
             const float* __restrict__ bias, __nv_bfloat16* __restrict__ Cb) {
    extern __shared__ __align__(16) char smraw[];
    GemmCtx<HH> cx;
    cx.init(A, BT, su32(smraw));
    float acc[2][8][4];
    cx.run(acc, bias);

#pragma unroll
    for (int mt = 0; mt < 2; mt++)
#pragma unroll
        for (int nt = 0; nt < 8; nt++) {
            const int col = cx.col0 + cx.wn * 64 + nt * 8 + cx.tig * 2;
            const int r0 = cx.row0 + cx.wm * 32 + mt * 16 + cx.gid;
            const int r1 = r0 + 8;
            __nv_bfloat162 p01 = __floats2bfloat162_rn(tanh_fast(acc[mt][nt][0]),
                                                       tanh_fast(acc[mt][nt][1]));
            __nv_bfloat162 p23 = __floats2bfloat162_rn(tanh_fast(acc[mt][nt][2]),
                                                       tanh_fast(acc[mt][nt][3]));
            *reinterpret_cast<__nv_bfloat162*>(Cb + (size_t)r0 * HH + col) = p01;
            *reinterpret_cast<__nv_bfloat162*>(Cb + (size_t)r1 * HH + col) = p23;
        }
}

// ---------------------------------------------------------------------------
// GEMM2 fused: logits stay on-chip. Emits (max,sumexp) partials + gathered
// logit values at this CTA's target labels. NO global logits array.
// ---------------------------------------------------------------------------
__global__ void __launch_bounds__(256)
gemm2_fused(const __nv_bfloat16* __restrict__ A, const __nv_bfloat16* __restrict__ BT,
            const float* __restrict__ bias, const int* __restrict__ targets) {
    extern __shared__ __align__(16) char smraw[];
    GemmCtx<HH> cx;
    cx.init(A, BT, su32(smraw));
    float acc[2][8][4];
    cx.run(acc, bias);

    const int lane = cx.lane, warp = cx.warp, wm = cx.wm, wn = cx.wn;
    const int gid = cx.gid, tig = cx.tig, row0 = cx.row0, col0 = cx.col0;

    // ---- per-row (max, sumexp) partials over this warp's 64-col span
#pragma unroll
    for (int mt = 0; mt < 2; mt++) {
#pragma unroll
        for (int half = 0; half < 2; half++) {
            float m = -INFINITY;
#pragma unroll
            for (int nt = 0; nt < 8; nt++)
                m = fmaxf(m, fmaxf(acc[mt][nt][half * 2], acc[mt][nt][half * 2 + 1]));
            float s = 0.f;
#pragma unroll
            for (int nt = 0; nt < 8; nt++)
                s += __expf(acc[mt][nt][half * 2] - m) + __expf(acc[mt][nt][half * 2 + 1] - m);
#pragma unroll
            for (int o = 1; o <= 2; o <<= 1) {
                const float mo = __shfl_xor_sync(0xffffffffu, m, o);
                const float so = __shfl_xor_sync(0xffffffffu, s, o);
                const float mn = fmaxf(m, mo);
                s = s * __expf(m - mn) + so * __expf(mo - mn);
                m = mn;
            }
            if (tig == 0) {
                const int row = row0 + wm * 32 + mt * 16 + gid + half * 8;
                g_part[row][blockIdx.x * 2 + wn] = make_float2(m, s);
            }
        }
    }

    // ---- stage logits block to smem (pipeline stages are dead after a barrier)
    __syncthreads();
    float* sl = reinterpret_cast<float*>(smraw);
#pragma unroll
    for (int mt = 0; mt < 2; mt++)
#pragma unroll
        for (int nt = 0; nt < 8; nt++) {
            const int c = wn * 64 + nt * 8 + tig * 2;
            const int r0 = wm * 32 + mt * 16 + gid;
            const int r1 = r0 + 8;
            sl[r0 * SLSTR + c]     = acc[mt][nt][0];
            sl[r0 * SLSTR + c + 1] = acc[mt][nt][1];
            sl[r1 * SLSTR + c]     = acc[mt][nt][2];
            sl[r1 * SLSTR + c + 1] = acc[mt][nt][3];
        }

    // ---- warp 0: compact list of label indices landing in [col0, col0+128)
    const int b = row0 >> 10;                 // T = 1024
    const int* tg = targets + (b << 7);
    int* s_cnt  = reinterpret_cast<int*>(smraw + LIST_OFF);
    int* s_list = s_cnt + 4;
    if (warp == 0) {
        int cnt = 0;
        const unsigned lt = (1u << lane) - 1u;
#pragma unroll
        for (int it = 0; it < 4; it++) {
            const int i = it * 32 + lane;
            const int lab = tg[i];
            const bool in = (lab >= col0) && (lab < col0 + 128);
            const unsigned mask = __ballot_sync(0xffffffffu, in);
            if (in) s_list[cnt + __popc(mask & lt)] = (i << 16) | (lab - col0);
            cnt += __popc(mask);
        }
        if (lane == 0) *s_cnt = cnt;
    }
    __syncthreads();
    const int cnt = *s_cnt;

    // ---- scatter gathered logits: 8 warps x 16 rows
#pragma unroll 1
    for (int rr = 0; rr < 16; rr++) {
        const int r = warp * 16 + rr;
        float* grow = g_gath + (size_t)(row0 + r) * PST;
        for (int e = lane; e < cnt; e += 32) {
            const int packed = s_list[e];
            grow[packed >> 16] = sl[r * SLSTR + (packed & 0xffff)];
        }
        if (col0 == 0 && lane == 0) grow[128] = sl[r * SLSTR];   // blank = col 0
    }
}

// ---------------------------------------------------------------------------
// lse from partials + p = exp(gath - lse). Warp per row; fully coalesced.
// ---------------------------------------------------------------------------
__global__ void __launch_bounds__(256)
lse_finish_kernel() {
    const int warp = threadIdx.x >> 5;
    const int lane = threadIdx.x & 31;
    const int row  = (blockIdx.x << 3) + warp;

    float m = -INFINITY, s = 0.f;
    if (lane < 16) {
        const float2 p = g_part[row][lane];
        m = p.x; s = p.y;
    }
#pragma unroll
    for (int o = 16; o > 0; o >>= 1) {
        const float mo = __shfl_xor_sync(0xffffffffu, m, o);
        const float so = __shfl_xor_sync(0xffffffffu, s, o);
        const float mn = fmaxf(m, mo);
        s = s * __expf(m - mn) + so * __expf(mo - mn);
        m = mn;
    }
    const float lse = m + logf(s);

    const float* gr = g_gath + (size_t)row * PST;
    float* pr = g_p2 + (size_t)row * PST;
    const float4 v = reinterpret_cast<const float4*>(gr)[lane];
    float4 p;
    p.x = expf(v.x - lse); p.y = expf(v.y - lse);
    p.z = expf(v.z - lse); p.w = expf(v.w - lse);
    reinterpret_cast<float4*>(pr)[lane] = p;
    if (lane == 0) pr[128] = expf(gr[128] - lse);
}

// ---------------------------------------------------------------------------
// Linear-domain CTC forward scan: one WARP per batch element.
// 16-slot register prefetch ring (~960 cyc cover > worst-case DRAM latency).
// Renorm fires only at unrolled slots 6 and 14 (t = 2+16k+i ≡ 0 mod 8).
// ---------------------------------------------------------------------------
__global__ void __launch_bounds__(32)
ctc_lin_kernel(const int* __restrict__ targets, const int* __restrict__ input_lengths,
               float* __restrict__ out) {
    const int b    = blockIdx.x;
    const int lane = threadIdx.x;
    const int* tg  = targets + b * SS;
    const float* base = g_p2 + (size_t)b * TT * PST;
    const int Tlen = input_lengths[b];

    float c1 = 0.f, c3 = 0.f, c5 = 0.f, c7 = 0.f;
    {
        const int s1 = lane * 8 + 1;
        if (s1 >= 3)            c1 = (tg[s1 >> 1] != tg[(s1 >> 1) - 1]) ? 1.f : 0.f;
        const int s3 = lane * 8 + 3;
        c3 = (tg[s3 >> 1] != tg[(s3 >> 1) - 1]) ? 1.f : 0.f;
        const int s5 = lane * 8 + 5;
        c5 = (tg[s5 >> 1] != tg[(s5 >> 1) - 1]) ? 1.f : 0.f;
        const int s7 = lane * 8 + 7;
        c7 = (tg[s7 >> 1] != tg[(s7 >> 1) - 1]) ? 1.f : 0.f;
    }

    const float init_sc = __int_as_float((100 + 127) << 23);
    float r[9];
#pragma unroll
    for (int j = 0; j < 9; j++) r[j] = 0.f;
    if (lane == 0) {
        r[0] = base[128] * init_sc;   // s=0 blank
        r[1] = base[0]   * init_sc;   // s=1 first label
    }
    int Esum = 100;

    float4 F[16];
    float  P[16];

#define LOADSLOT(i, tp_) do {                                                 \
        int tp = (tp_); if (tp > Tlen - 1) tp = Tlen - 1;                     \
        const float* rp = base + (size_t)tp * PST;                            \
        F[i] = *reinterpret_cast<const float4*>(rp + lane * 4);               \
        P[i] = rp[128];                                                       \
    } while (0)

// s-1 for j=0 AND s-2 for j=1 are BOTH the previous lane's r[7] (= u1).
#define STEP(i) do {                                                          \
        const float4 Ff = F[i]; const float Pf = P[i];                        \
        float u1 = __shfl_up_sync(0xffffffffu, r[7], 1);                      \
        if (lane == 0) u1 = 0.f;                                              \
        float n0 = (r[0] + u1) * Pf;                                          \
        float n1 = fmaf(c1, u1,   r[1] + r[0]) * Ff.x;                        \
        float n2 = (r[2] + r[1]) * Pf;                                        \
        float n3 = fmaf(c3, r[1], r[3] + r[2]) * Ff.y;                        \
        float n4 = (r[4] + r[3]) * Pf;                                        \
        float n5 = fmaf(c5, r[3], r[5] + r[4]) * Ff.z;                        \
        float n6 = (r[6] + r[5]) * Pf;                                        \
        float n7 = fmaf(c7, r[5], r[7] + r[6]) * Ff.w;                        \
        float n8 = (r[8] + r[7]) * Pf;                                        \
        r[0]=n0; r[1]=n1; r[2]=n2; r[3]=n3; r[4]=n4;                          \
        r[5]=n5; r[6]=n6; r[7]=n7;                                            \
        r[8] = (lane == 31) ? n8 : 0.f;                                       \
    } while (0)

#define RENORM() do {                                                         \
        float m = r[0];                                                       \
        m = fmaxf(m, r[1]); m = fmaxf(m, r[2]); m = fmaxf(m, r[3]);           \
        m = fmaxf(m, r[4]); m = fmaxf(m, r[5]); m = fmaxf(m, r[6]);           \
        m = fmaxf(m, r[7]); m = fmaxf(m, r[8]);                               \
        m = fmaxf(m, __shfl_xor_sync(0xffffffffu, m, 16));                    \
        m = fmaxf(m, __shfl_xor_sync(0xffffffffu, m, 8));                     \
        m = fmaxf(m, __shfl_xor_sync(0xffffffffu, m, 4));                     \
        m = fmaxf(m, __shfl_xor_sync(0xffffffffu, m, 2));                    \
        m = fmaxf(m, __shfl_xor_sync(0xffffffffu, m, 1));                    \
        int ex = (__float_as_int(m) >> 23) & 255;                             \
        int se = 60 - (ex - 127);                                             \
        se = (se > 127) ? 127 : ((se < -126) ? -126 : se);                    \
        const float sc = __int_as_float((se + 127) << 23);                    \
        r[0]*=sc; r[1]*=sc; r[2]*=sc; r[3]*=sc; r[4]*=sc;                     \
        r[5]*=sc; r[6]*=sc; r[7]*=sc; r[8]*=sc;                               \
        Esum += se;                                                           \
    } while (0)

    int t = 1;
#pragma unroll
    for (int i = 0; i < 16; i++) LOADSLOT(i, 1 + i);

    if (Tlen > 1) {
        bool run = true;
        while (run) {
#pragma unroll
            for (int i = 0; i < 16; i++) {
                STEP(i);
                LOADSLOT(i, t + 16);
                if (++t >= Tlen) { run = false; break; }
                // t = 2 + 16k + i here; (t & 7) == 0 iff i == 6 or i == 14
                if (i == 6 || i == 14) RENORM();
            }
        }
    }

    __shared__ float fin[260];
#pragma unroll
    for (int j = 0; j < 8; j++) fin[lane * 8 + j] = r[j];
    if (lane == 31) fin[256] = r[8];
    __syncwarp();

    int cnt = 0;
#pragma unroll
    for (int i = 0; i < 4; i++) cnt += (tg[lane + i * 32] != 0);
#pragma unroll
    for (int o = 16; o > 0; o >>= 1) cnt += __shfl_xor_sync(0xffffffffu, cnt, o);
    const int sb = cnt;

    if (lane == 0) {
        const float e = fin[2 * sb - 1] + fin[2 * sb];
        out[b] = ((float)Esum * 0.6931471805599453f - logf(e)) / (float)sb;
    }
}

// ---------------------------------------------------------------------------
extern "C" void kernel_launch(void* const* d_in, const int* in_sizes, int n_in,
                              void* d_out, int out_size) {
    const int*   targets = (const int*)  d_in[0];
    const float* X       = (const float*)d_in[1];
    const int*   ilen    = (const int*)  d_in[2];
    const float* W1      = (const float*)d_in[3];
    const float* b1      = (const float*)d_in[4];
    const float* W2      = (const float*)d_in[5];
    const float* b2      = (const float*)d_in[6];
    float*       out     = (float*)d_out;

    const int M = BB * TT;  // 32768

    __nv_bfloat16 *xb, *w1t, *w2t, *hb;
    cudaGetSymbolAddress((void**)&xb,  g_Xb);
    cudaGetSymbolAddress((void**)&w1t, g_W1t);
    cudaGetSymbolAddress((void**)&w2t, g_W2t);
    cudaGetSymbolAddress((void**)&hb,  g_hb);

    f2bf_kernel<<<(M * HH) / (256 * 4), 256>>>(X, xb, M * HH);
    f2bfT_kernel<<<dim3(HH / 32, HH / 32), 256>>>(W1, w1t, HH, HH);
    f2bfT_kernel<<<dim3(VV / 32, HH / 32), 256>>>(W2, w2t, HH, VV);

    cudaFuncSetAttribute(gemm1_kernel, cudaFuncAttributeMaxDynamicSharedMemorySize, GSM);
    cudaFuncSetAttribute(gemm2_fused,  cudaFuncAttributeMaxDynamicSharedMemorySize, GSM);

    gemm1_kernel<<<dim3(HH / 128, M / 128), 256, GSM>>>(xb, w1t, b1, hb);
    gemm2_fused<<<dim3(VV / 128, M / 128), 256, GSM>>>(hb, w2t, b2, targets);

    lse_finish_kernel<<<M / 8, 256>>>();

    ctc_lin_kernel<<<BB, 32>>>(targets, ilen, out);
}

// round 17
// speedup vs baseline: 1.6247x; 1.1982x over previous
#include <cuda_runtime.h>
#include <cuda_bf16.h>
#include <math.h>
#include <stdint.h>

// Problem constants
#define BB 32
#define TT 1024
#define HH 512
#define VV 1024
#define SS 128
#define LL 257          // 2*S + 1
#define PST 132         // compact row stride (floats): 128 odd entries + blank + pad

// GEMM tile config: 128x128 tile, 512 threads (16 warps, warp tile 32x32)
#define BK 64
#define ASTR 72                      // halves per padded tile row (144 B)
#define TILE_H (128 * ASTR)          // halves per tile
#define NSTG 3
#define STG_B (2 * TILE_H * 2)       // bytes per stage (A+B) = 36864
#define GSM (NSTG * STG_B)           // 110592 bytes dynamic smem

#define SLSTR 129                    // floats per staged-logits row
#define SL_BYTES (128 * SLSTR * 4)   // 66048
#define LIST_OFF SL_BYTES

// Scratch (device globals: allocation-free per harness rules)
__device__ __nv_bfloat16 g_Xb[(size_t)BB * TT * HH];   // 32 MB : X bf16 (K-major)
__device__ __nv_bfloat16 g_W1t[(size_t)HH * HH];       // W1^T bf16 [N][K]
__device__ __nv_bfloat16 g_W2t[(size_t)VV * HH];       // W2^T bf16 [N][K]
__device__ __nv_bfloat16 g_hb[(size_t)BB * TT * HH];   // 32 MB : tanh(X@W1+b1) bf16
__device__ float2 g_part[(size_t)BB * TT][32];         // 8 MB  : per-row (max, sumexp), 32-col spans
__device__ float g_gath[(size_t)BB * TT * PST + 64];   // 17 MB : gathered logits
__device__ float g_p2[(size_t)BB * TT * PST + 64];     // 17 MB : compact probs

// ---------------------------------------------------------------------------
// PTX helpers
// ---------------------------------------------------------------------------
__device__ __forceinline__ unsigned su32(const void* p) {
    unsigned a;
    asm("{ .reg .u64 t; cvta.to.shared.u64 t, %1; cvt.u32.u64 %0, t; }" : "=r"(a) : "l"(p));
    return a;
}
__device__ __forceinline__ void cp16(unsigned dst, const void* src) {
    asm volatile("cp.async.cg.shared.global [%0], [%1], 16;" :: "r"(dst), "l"(src));
}
__device__ __forceinline__ void cp_commit() { asm volatile("cp.async.commit_group;" ::: "memory"); }
__device__ __forceinline__ void cp_wait1()  { asm volatile("cp.async.wait_group 1;" ::: "memory"); }
__device__ __forceinline__ void cp_wait0()  { asm volatile("cp.async.wait_group 0;" ::: "memory"); }

__device__ __forceinline__ void ldm_x4(unsigned* r, unsigned addr) {
    asm volatile("ldmatrix.sync.aligned.m8n8.x4.shared.b16 {%0,%1,%2,%3}, [%4];"
        : "=r"(r[0]), "=r"(r[1]), "=r"(r[2]), "=r"(r[3]) : "r"(addr));
}
__device__ __forceinline__ void mma16816(float* c, const unsigned* a, const unsigned* b) {
    asm volatile(
        "mma.sync.aligned.m16n8k16.row.col.f32.bf16.bf16.f32 "
        "{%0,%1,%2,%3}, {%4,%5,%6,%7}, {%8,%9}, {%0,%1,%2,%3};"
        : "+f"(c[0]), "+f"(c[1]), "+f"(c[2]), "+f"(c[3])
        : "r"(a[0]), "r"(a[1]), "r"(a[2]), "r"(a[3]), "r"(b[0]), "r"(b[1]));
}
__device__ __forceinline__ float tanh_fast(float x) {
    float y;
    asm("tanh.approx.f32 %0, %1;" : "=f"(y) : "f"(x));
    return y;
}

// ---------------------------------------------------------------------------
// Conversion kernels
// ---------------------------------------------------------------------------
__global__ void __launch_bounds__(256)
f2bf_kernel(const float* __restrict__ in, __nv_bfloat16* __restrict__ out, int n) {
    int i = (blockIdx.x * 256 + threadIdx.x) * 4;
    if (i < n) {
        float4 v = *reinterpret_cast<const float4*>(in + i);
        *reinterpret_cast<__nv_bfloat162*>(out + i)     = __floats2bfloat162_rn(v.x, v.y);
        *reinterpret_cast<__nv_bfloat162*>(out + i + 2) = __floats2bfloat162_rn(v.z, v.w);
    }
}

// transpose + convert: in [K][N] fp32 row-major -> out [N][K] bf16 row-major
__global__ void __launch_bounds__(256)
f2bfT_kernel(const float* __restrict__ in, __nv_bfloat16* __restrict__ out, int K, int N) {
    __shared__ float tile[32][33];
    const int n0 = blockIdx.x * 32, k0 = blockIdx.y * 32;
    const int tx = threadIdx.x & 31, ty = threadIdx.x >> 5;
#pragma unroll
    for (int i = 0; i < 32; i += 8)
        tile[ty + i][tx] = in[(size_t)(k0 + ty + i) * N + n0 + tx];
    __syncthreads();
#pragma unroll
    for (int i = 0; i < 32; i += 8)
        out[(size_t)(n0 + ty + i) * K + k0 + tx] = __float2bfloat16(tile[tx][ty + i]);
}

// ---------------------------------------------------------------------------
// Shared GEMM mainloop: 128x128 tile, BK=64, 3-stage cp.async, single barrier
// per chunk, 512 threads / 16 warps, warp tile 32x32.
// Leaves logits+bias in acc[2][4][4].
// ---------------------------------------------------------------------------
template <int KDIM>
struct GemmCtx {
    unsigned sbase;
    int lane, warp, wm, wn, gid, tig, row0, col0;
    unsigned aoff[2], boff[2];
    const __nv_bfloat16 *Ap, *Bp;
    int frow, fg0;

    __device__ __forceinline__ void init(const __nv_bfloat16* A, const __nv_bfloat16* BT,
                                         unsigned sb) {
        sbase = sb;
        const int tid = threadIdx.x;
        lane = tid & 31; warp = tid >> 5;
        wm = warp & 3;   wn = warp >> 2;   // 4 m-groups x 4 n-groups
        gid = lane >> 2; tig = lane & 3;
        row0 = blockIdx.y * 128; col0 = blockIdx.x * 128;
        const int l8 = lane & 7, j = lane >> 3;
#pragma unroll
        for (int mt = 0; mt < 2; mt++) {
            const int r = wm * 32 + mt * 16 + (j & 1) * 8 + l8;
            aoff[mt] = (unsigned)((r * ASTR + (j >> 1) * 8) * 2);
        }
#pragma unroll
        for (int np = 0; np < 2; np++) {
            const int r = wn * 32 + np * 16 + (j >> 1) * 8 + l8;
            boff[np] = (unsigned)((r * ASTR + (j & 1) * 8) * 2);
        }
        frow = tid >> 2; fg0 = (tid & 3) << 1;   // 2 granules of 8 per tensor
        Ap = A  + (size_t)(row0 + frow) * KDIM;
        Bp = BT + (size_t)(col0 + frow) * KDIM;
    }

    __device__ __forceinline__ void issue(int c) {
        const unsigned abase = sbase + (unsigned)(c % NSTG) * STG_B;
        const unsigned bbase = abase + TILE_H * 2u;
        const unsigned rowoff = (unsigned)(frow * ASTR * 2);
        const int k0 = c * BK;
#pragma unroll
        for (int g = 0; g < 2; g++) {
            const int kk = (fg0 + g) * 8;
            cp16(abase + rowoff + (unsigned)(fg0 + g) * 16u, Ap + k0 + kk);
            cp16(bbase + rowoff + (unsigned)(fg0 + g) * 16u, Bp + k0 + kk);
        }
        cp_commit();
    }

    __device__ __forceinline__ void run(float (&acc)[2][4][4], const float* bias) {
#pragma unroll
        for (int mt = 0; mt < 2; mt++)
#pragma unroll
            for (int nt = 0; nt < 4; nt++)
#pragma unroll
                for (int e = 0; e < 4; e++) acc[mt][nt][e] = 0.f;

        issue(0); issue(1);
        const int NC = KDIM / BK;
#pragma unroll 1
        for (int c = 0; c < NC; ++c) {
            if (c < NC - 1) cp_wait1(); else cp_wait0();
            __syncthreads();
            if (c + 2 < NC) issue(c + 2);

            const unsigned Au = sbase + (unsigned)(c % NSTG) * STG_B;
            const unsigned Bu = Au + TILE_H * 2u;
#pragma unroll
            for (int kk = 0; kk < BK / 16; kk++) {
                const unsigned kbb = (unsigned)(kk * 32);
                unsigned af[2][4];
                ldm_x4(af[0], Au + aoff[0] + kbb);
                ldm_x4(af[1], Au + aoff[1] + kbb);
                unsigned bf[2][4];
                ldm_x4(bf[0], Bu + boff[0] + kbb);
                ldm_x4(bf[1], Bu + boff[1] + kbb);
#pragma unroll
                for (int mt = 0; mt < 2; mt++)
#pragma unroll
                    for (int nt = 0; nt < 4; nt++)
                        mma16816(acc[mt][nt], af[mt], &bf[nt >> 1][(nt & 1) * 2]);
            }
        }
        // add bias
#pragma unroll
        for (int mt = 0; mt < 2; mt++)
#pragma unroll
            for (int nt = 0; nt < 4; nt++) {
                const int col = col0 + wn * 32 + nt * 8 + tig * 2;
                const float bx = bias[col], by = bias[col + 1];
                acc[mt][nt][0] += bx; acc[mt][nt][1] += by;
                acc[mt][nt][2] += bx; acc[mt][nt][3] += by;
            }
    }
};

// ---------------------------------------------------------------------------
// GEMM1: h = tanh(X@W1+b1), bf16 output
// ---------------------------------------------------------------------------
__global__ void __launch_bounds__(512, 2)
gemm1_kernel(const __nv_bfloat16* __restrict__ A, const __nv_bfloat16* __restrict__ BT,
             const float* __restrict__ bias, __nv_bfloat16* __restrict__ Cb) {
    extern __shared__ __align__(16) char smraw[];
    GemmCtx<HH> cx;
    cx.init(A, BT, su32(smraw));
    float acc[2][4][4];
    cx.run(acc, bias);

#pragma unroll
    for (int mt = 0; mt < 2; mt++)
#pragma unroll
        for (int nt = 0; nt < 4; nt++) {
            const int col = cx.col0 + cx.wn * 32 + nt * 8 + cx.tig * 2;
            const int r0 = cx.row0 + cx.wm * 32 + mt * 16 + cx.gid;
            const int r1 = r0 + 8;
            __nv_bfloat162 p01 = __floats2bfloat162_rn(tanh_fast(acc[mt][nt][0]),
                                                       tanh_fast(acc[mt][nt][1]));
            __nv_bfloat162 p23 = __floats2bfloat162_rn(tanh_fast(acc[mt][nt][2]),
                                                       tanh_fast(acc[mt][nt][3]));
            *reinterpret_cast<__nv_bfloat162*>(Cb + (size_t)r0 * HH + col) = p01;
            *reinterpret_cast<__nv_bfloat162*>(Cb + (size_t)r1 * HH + col) = p23;
        }
}

// ---------------------------------------------------------------------------
// GEMM2 fused: logits stay on-chip. Emits (max,sumexp) partials (32-col spans)
// + gathered logit values at this CTA's target labels.
// ---------------------------------------------------------------------------
__global__ void __launch_bounds__(512, 2)
gemm2_fused(const __nv_bfloat16* __restrict__ A, const __nv_bfloat16* __restrict__ BT,
            const float* __restrict__ bias, const int* __restrict__ targets) {
    extern __shared__ __align__(16) char smraw[];
    GemmCtx<HH> cx;
    cx.init(A, BT, su32(smraw));
    float acc[2][4][4];
    cx.run(acc, bias);

    const int lane = cx.lane, warp = cx.warp, wm = cx.wm, wn = cx.wn;
    const int gid = cx.gid, tig = cx.tig, row0 = cx.row0, col0 = cx.col0;

    // ---- per-row (max, sumexp) partials over this warp's 32-col span
#pragma unroll
    for (int mt = 0; mt < 2; mt++) {
#pragma unroll
        for (int half = 0; half < 2; half++) {
            float m = -INFINITY;
#pragma unroll
            for (int nt = 0; nt < 4; nt++)
                m = fmaxf(m, fmaxf(acc[mt][nt][half * 2], acc[mt][nt][half * 2 + 1]));
            float s = 0.f;
#pragma unroll
            for (int nt = 0; nt < 4; nt++)
                s += __expf(acc[mt][nt][half * 2] - m) + __expf(acc[mt][nt][half * 2 + 1] - m);
#pragma unroll
            for (int o = 1; o <= 2; o <<= 1) {
                const float mo = __shfl_xor_sync(0xffffffffu, m, o);
                const float so = __shfl_xor_sync(0xffffffffu, s, o);
                const float mn = fmaxf(m, mo);
                s = s * __expf(m - mn) + so * __expf(mo - mn);
                m = mn;
            }
            if (tig == 0) {
                const int row = row0 + wm * 32 + mt * 16 + half * 8 + gid;
                g_part[row][blockIdx.x * 4 + wn] = make_float2(m, s);
            }
        }
    }

    // ---- stage logits block to smem (pipeline stages are dead after a barrier)
    __syncthreads();
    float* sl = reinterpret_cast<float*>(smraw);
#pragma unroll
    for (int mt = 0; mt < 2; mt++)
#pragma unroll
        for (int nt = 0; nt < 4; nt++) {
            const int c = wn * 32 + nt * 8 + tig * 2;
            const int r0 = wm * 32 + mt * 16 + gid;
            const int r1 = r0 + 8;
            sl[r0 * SLSTR + c]     = acc[mt][nt][0];
            sl[r0 * SLSTR + c + 1] = acc[mt][nt][1];
            sl[r1 * SLSTR + c]     = acc[mt][nt][2];
            sl[r1 * SLSTR + c + 1] = acc[mt][nt][3];
        }

    // ---- warp 0: compact list of label indices landing in [col0, col0+128)
    const int b = row0 >> 10;                 // T = 1024
    const int* tg = targets + (b << 7);
    int* s_cnt  = reinterpret_cast<int*>(smraw + LIST_OFF);
    int* s_list = s_cnt + 4;
    if (warp == 0) {
        int cnt = 0;
        const unsigned lt = (1u << lane) - 1u;
#pragma unroll
        for (int it = 0; it < 4; it++) {
            const int i = it * 32 + lane;
            const int lab = tg[i];
            const bool in = (lab >= col0) && (lab < col0 + 128);
            const unsigned mask = __ballot_sync(0xffffffffu, in);
            if (in) s_list[cnt + __popc(mask & lt)] = (i << 16) | (lab - col0);
            cnt += __popc(mask);
        }
        if (lane == 0) *s_cnt = cnt;
    }
    __syncthreads();
    const int cnt = *s_cnt;

    // ---- scatter gathered logits: 16 warps x 8 rows
#pragma unroll 1
    for (int rr = 0; rr < 8; rr++) {
        const int r = warp * 8 + rr;
        float* grow = g_gath + (size_t)(row0 + r) * PST;
        for (int e = lane; e < cnt; e += 32) {
            const int packed = s_list[e];
            grow[packed >> 16] = sl[r * SLSTR + (packed & 0xffff)];
        }
        if (col0 == 0 && lane == 0) grow[128] = sl[r * SLSTR];   // blank = col 0
    }
}

// ---------------------------------------------------------------------------
// lse from 32 partials + p = exp(gath - lse). Warp per row; fully coalesced.
// ---------------------------------------------------------------------------
__global__ void __launch_bounds__(256)
lse_finish_kernel() {
    const int warp = threadIdx.x >> 5;
    const int lane = threadIdx.x & 31;
    const int row  = (blockIdx.x << 3) + warp;

    const float2 pp = g_part[row][lane];
    float m = pp.x, s = pp.y;
#pragma unroll
    for (int o = 16; o > 0; o >>= 1) {
        const float mo = __shfl_xor_sync(0xffffffffu, m, o);
        const float so = __shfl_xor_sync(0xffffffffu, s, o);
        const float mn = fmaxf(m, mo);
        s = s * __expf(m - mn) + so * __expf(mo - mn);
        m = mn;
    }
    const float lse = m + logf(s);

    const float* gr = g_gath + (size_t)row * PST;
    float* pr = g_p2 + (size_t)row * PST;
    const float4 v = reinterpret_cast<const float4*>(gr)[lane];
    float4 p;
    p.x = expf(v.x - lse); p.y = expf(v.y - lse);
    p.z = expf(v.z - lse); p.w = expf(v.w - lse);
    reinterpret_cast<float4*>(pr)[lane] = p;
    if (lane == 0) pr[128] = expf(gr[128] - lse);
}

// ---------------------------------------------------------------------------
// Linear-domain CTC forward scan: one WARP per batch element.
// 32-slot register prefetch ring. Renorm at unrolled slots i in {6,14,22,30}
// (t = 2 + 32k + i, so (t & 7) == 0 exactly there).
// ---------------------------------------------------------------------------
__global__ void __launch_bounds__(32)
ctc_lin_kernel(const int* __restrict__ targets, const int* __restrict__ input_lengths,
               float* __restrict__ out) {
    const int b    = blockIdx.x;
    const int lane = threadIdx.x;
    const int* tg  = targets + b * SS;
    const float* base = g_p2 + (size_t)b * TT * PST;
    const int Tlen = input_lengths[b];

    float c1 = 0.f, c3 = 0.f, c5 = 0.f, c7 = 0.f;
    {
        const int s1 = lane * 8 + 1;
        if (s1 >= 3)            c1 = (tg[s1 >> 1] != tg[(s1 >> 1) - 1]) ? 1.f : 0.f;
        const int s3 = lane * 8 + 3;
        c3 = (tg[s3 >> 1] != tg[(s3 >> 1) - 1]) ? 1.f : 0.f;
        const int s5 = lane * 8 + 5;
        c5 = (tg[s5 >> 1] != tg[(s5 >> 1) - 1]) ? 1.f : 0.f;
        const int s7 = lane * 8 + 7;
        c7 = (tg[s7 >> 1] != tg[(s7 >> 1) - 1]) ? 1.f : 0.f;
    }

    const float init_sc = __int_as_float((100 + 127) << 23);
    float r[9];
#pragma unroll
    for (int j = 0; j < 9; j++) r[j] = 0.f;
    if (lane == 0) {
        r[0] = base[128] * init_sc;   // s=0 blank
        r[1] = base[0]   * init_sc;   // s=1 first label
    }
    int Esum = 100;

    float4 F[32];
    float  P[32];

#define LOADSLOT(i, tp_) do {                                                 \
        int tp = (tp_); if (tp > Tlen - 1) tp = Tlen - 1;                     \
        const float* rp = base + (size_t)tp * PST;                            \
        F[i] = *reinterpret_cast<const float4*>(rp + lane * 4);               \
        P[i] = rp[128];                                                       \
    } while (0)

// s-1 for j=0 AND s-2 for j=1 are BOTH the previous lane's r[7] (= u1).
#define STEP(i) do {                                                          \
        const float4 Ff = F[i]; const float Pf = P[i];                        \
        float u1 = __shfl_up_sync(0xffffffffu, r[7], 1);                      \
        if (lane == 0) u1 = 0.f;                                              \
        float n0 = (r[0] + u1) * Pf;                                          \
        float n1 = fmaf(c1, u1,   r[1] + r[0]) * Ff.x;                        \
        float n2 = (r[2] + r[1]) * Pf;                                        \
        float n3 = fmaf(c3, r[1], r[3] + r[2]) * Ff.y;                        \
        float n4 = (r[4] + r[3]) * Pf;                                        \
        float n5 = fmaf(c5, r[3], r[5] + r[4]) * Ff.z;                        \
        float n6 = (r[6] + r[5]) * Pf;                                        \
        float n7 = fmaf(c7, r[5], r[7] + r[6]) * Ff.w;                        \
        float n8 = (r[8] + r[7]) * Pf;                                        \
        r[0]=n0; r[1]=n1; r[2]=n2; r[3]=n3; r[4]=n4;                          \
        r[5]=n5; r[6]=n6; r[7]=n7;                                            \
        r[8] = (lane == 31) ? n8 : 0.f;                                       \
    } while (0)

#define RENORM() do {                                                         \
        float m = r[0];                                                       \
        m = fmaxf(m, r[1]); m = fmaxf(m, r[2]); m = fmaxf(m, r[3]);           \
        m = fmaxf(m, r[4]); m = fmaxf(m, r[5]); m = fmaxf(m, r[6]);           \
        m = fmaxf(m, r[7]); m = fmaxf(m, r[8]);                               \
        m = fmaxf(m, __shfl_xor_sync(0xffffffffu, m, 16));                    \
        m = fmaxf(m, __shfl_xor_sync(0xffffffffu, m, 8));                     \
        m = fmaxf(m, __shfl_xor_sync(0xffffffffu, m, 4));                     \
        m = fmaxf(m, __shfl_xor_sync(0xffffffffu, m, 2));                    \
        m = fmaxf(m, __shfl_xor_sync(0xffffffffu, m, 1));                    \
        int ex = (__float_as_int(m) >> 23) & 255;                             \
        int se = 60 - (ex - 127);                                             \
        se = (se > 127) ? 127 : ((se < -126) ? -126 : se);                    \
        const float sc = __int_as_float((se + 127) << 23);                    \
        r[0]*=sc; r[1]*=sc; r[2]*=sc; r[3]*=sc; r[4]*=sc;                     \
        r[5]*=sc; r[6]*=sc; r[7]*=sc; r[8]*=sc;                               \
        Esum += se;                                                           \
    } while (0)

    int t = 1;
#pragma unroll
    for (int i = 0; i < 32; i++) LOADSLOT(i, 1 + i);

    if (Tlen > 1) {
        bool run = true;
        while (run) {
#pragma unroll
            for (int i = 0; i < 32; i++) {
                STEP(i);
                LOADSLOT(i, t + 32);
                if (++t >= Tlen) { run = false; break; }
                // t = 2 + 32k + i here; (t & 7) == 0 iff i % 8 == 6
                if (i == 6 || i == 14 || i == 22 || i == 30) RENORM();
            }
        }
    }

    __shared__ float fin[260];
#pragma unroll
    for (int j = 0; j < 8; j++) fin[lane * 8 + j] = r[j];
    if (lane == 31) fin[256] = r[8];
    __syncwarp();

    int cnt = 0;
#pragma unroll
    for (int i = 0; i < 4; i++) cnt += (tg[lane + i * 32] != 0);
#pragma unroll
    for (int o = 16; o > 0; o >>= 1) cnt += __shfl_xor_sync(0xffffffffu, cnt, o);
    const int sb = cnt;

    if (lane == 0) {
        const float e = fin[2 * sb - 1] + fin[2 * sb];
        out[b] = ((float)Esum * 0.6931471805599453f - logf(e)) / (float)sb;
    }
}

// ---------------------------------------------------------------------------
extern "C" void kernel_launch(void* const* d_in, const int* in_sizes, int n_in,
                              void* d_out, int out_size) {
    const int*   targets = (const int*)  d_in[0];
    const float* X       = (const float*)d_in[1];
    const int*   ilen    = (const int*)  d_in[2];
    const float* W1      = (const float*)d_in[3];
    const float* b1      = (const float*)d_in[4];
    const float* W2      = (const float*)d_in[5];
    const float* b2      = (const float*)d_in[6];
    float*       out     = (float*)d_out;

    const int M = BB * TT;  // 32768

    __nv_bfloat16 *xb, *w1t, *w2t, *hb;
    cudaGetSymbolAddress((void**)&xb,  g_Xb);
    cudaGetSymbolAddress((void**)&w1t, g_W1t);
    cudaGetSymbolAddress((void**)&w2t, g_W2t);
    cudaGetSymbolAddress((void**)&hb,  g_hb);

    f2bf_kernel<<<(M * HH) / (256 * 4), 256>>>(X, xb, M * HH);
    f2bfT_kernel<<<dim3(HH / 32, HH / 32), 256>>>(W1, w1t, HH, HH);
    f2bfT_kernel<<<dim3(VV / 32, HH / 32), 256>>>(W2, w2t, HH, VV);

    cudaFuncSetAttribute(gemm1_kernel, cudaFuncAttributeMaxDynamicSharedMemorySize, GSM);
    cudaFuncSetAttribute(gemm2_fused,  cudaFuncAttributeMaxDynamicSharedMemorySize, GSM);

    gemm1_kernel<<<dim3(HH / 128, M / 128), 512, GSM>>>(xb, w1t, b1, hb);
    gemm2_fused<<<dim3(VV / 128, M / 128), 512, GSM>>>(hb, w2t, b2, targets);

    lse_finish_kernel<<<M / 8, 256>>>();

    ctc_lin_kernel<<<BB, 32>>>(targets, ilen, out);
}